// round 17
// baseline (speedup 1.0000x reference)
#include <cuda_runtime.h>
#include <cuda_fp16.h>

#define NB 4
#define NR 2
#define NREF 4
#define IH 320
#define IW 320
#define HW (IH*IW)
#define NPIX (NB*NR*HW)
#define NIMG (NB*NREF)
// Padded paired-texel image: col p maps to x = p-1 (x in [-1, 320]),
// row q maps to y = q-1 (y in [-1, 321]). All OOB texels are zero.
#define PW 322
#define PH 323
#define PHW (PW*PH)

// Per-render-camera: M = inv(R)*inv(K) (9 floats) then v = inv(R)*t (3 floats)
__device__ float g_renderM[NB*NR][12];
// Per-(b,ref): P = K_ref*R_ref (9) then s = K_ref*t_ref (3)
__device__ float g_refP[NB*NREF][12];
// Padded paired fp16 texels: entry (img,q,p) = {rg(x), b(x)|0, rg(x+1), b(x+1)|0}
// for x = p-1, y = q-1, with any out-of-range texel = 0. One aligned 16B load
// covers both x-corners of a bilinear row; the zero border replaces all
// validity masks and index clamps.
__device__ uint4 g_imgp[NIMG*PHW];

__device__ __forceinline__ void inv3(const float* a, float* o) {
    float c00 = a[4]*a[8] - a[5]*a[7];
    float c10 = a[5]*a[6] - a[3]*a[8];
    float c20 = a[3]*a[7] - a[4]*a[6];
    float det = a[0]*c00 + a[1]*c10 + a[2]*c20;
    float id  = 1.0f/det;
    o[0] = c00*id;
    o[1] = (a[2]*a[7] - a[1]*a[8])*id;
    o[2] = (a[1]*a[5] - a[2]*a[4])*id;
    o[3] = c10*id;
    o[4] = (a[0]*a[8] - a[2]*a[6])*id;
    o[5] = (a[2]*a[3] - a[0]*a[5])*id;
    o[6] = c20*id;
    o[7] = (a[1]*a[6] - a[0]*a[7])*id;
    o[8] = (a[0]*a[4] - a[1]*a[3])*id;
}

__device__ __forceinline__ void precompute_thread(
    int t,
    const float* __restrict__ camK,  const float* __restrict__ camW,
    const float* __restrict__ camKr, const float* __restrict__ camWr)
{
    if (t < NB*NR) {
        const float* k = camK + t*9;
        const float* w = camW + t*12;   // rows: [R[i][0..2], t[i]]
        float R[9], tv[3];
        #pragma unroll
        for (int i = 0; i < 3; i++) {
            R[i*3+0] = w[i*4+0];
            R[i*3+1] = w[i*4+1];
            R[i*3+2] = w[i*4+2];
            tv[i]    = w[i*4+3];
        }
        float iK[9], iR[9];
        inv3(k, iK);
        inv3(R, iR);
        float* o = g_renderM[t];
        #pragma unroll
        for (int i = 0; i < 3; i++) {
            #pragma unroll
            for (int j = 0; j < 3; j++)
                o[i*3+j] = iR[i*3+0]*iK[0+j] + iR[i*3+1]*iK[3+j] + iR[i*3+2]*iK[6+j];
            o[9+i] = iR[i*3+0]*tv[0] + iR[i*3+1]*tv[1] + iR[i*3+2]*tv[2];
        }
    } else if (t < NB*NR + NB*NREF) {
        int j = t - NB*NR;
        const float* k = camKr + j*9;
        const float* w = camWr + j*12;
        float* o = g_refP[j];
        #pragma unroll
        for (int i = 0; i < 3; i++) {
            #pragma unroll
            for (int c = 0; c < 3; c++)
                o[i*3+c] = k[i*3+0]*w[0*4+c] + k[i*3+1]*w[1*4+c] + k[i*3+2]*w[2*4+c];
            o[9+i] = k[i*3+0]*w[0*4+3] + k[i*3+1]*w[1*4+3] + k[i*3+2]*w[2*4+3];
        }
    }
}

// Planar f32 (img,c,y,x) -> padded paired fp16 AoS. Border entries are zero.
// Block 0 additionally computes the folded camera matrices (consumed only by
// render_kernel, which launches after this kernel).
__global__ void __launch_bounds__(256) interleave_kernel(
    const float* __restrict__ src,
    const float* __restrict__ camK,  const float* __restrict__ camW,
    const float* __restrict__ camKr, const float* __restrict__ camWr)
{
    if (blockIdx.x == 0 && threadIdx.x < NB*NR + NB*NREF)
        precompute_thread(threadIdx.x, camK, camW, camKr, camWr);

    int i = blockIdx.x * blockDim.x + threadIdx.x;
    if (i >= NIMG*PHW) return;
    int img = i / PHW;
    int rem = i - img*PHW;
    int q   = rem / PW;      // padded row
    int p   = rem - q*PW;    // padded col
    int y   = q - 1;
    int x   = p - 1;

    uint4 o = make_uint4(0u, 0u, 0u, 0u);
    if (y >= 0 && y < IH) {
        const float* base = src + (size_t)img*3*HW + y*IW;
        float r0 = 0.f, g0 = 0.f, b0 = 0.f, r1 = 0.f, g1 = 0.f, b1 = 0.f;
        if (x >= 0 && x < IW) {
            r0 = __ldg(base + x);
            g0 = __ldg(base + HW + x);
            b0 = __ldg(base + 2*HW + x);
        }
        int x1 = x + 1;
        if (x1 >= 0 && x1 < IW) {
            r1 = __ldg(base + x1);
            g1 = __ldg(base + HW + x1);
            b1 = __ldg(base + 2*HW + x1);
        }
        __half2 rg0 = __floats2half2_rn(r0, g0);
        __half2 bz0 = __floats2half2_rn(b0, 0.0f);
        __half2 rg1 = __floats2half2_rn(r1, g1);
        __half2 bz1 = __floats2half2_rn(b1, 0.0f);
        o.x = *reinterpret_cast<const unsigned int*>(&rg0);
        o.y = *reinterpret_cast<const unsigned int*>(&bz0);
        o.z = *reinterpret_cast<const unsigned int*>(&rg1);
        o.w = *reinterpret_cast<const unsigned int*>(&bz1);
    }
    g_imgp[i] = o;
}

__device__ __forceinline__ float2 h2f2(unsigned int u) {
    return __half22float2(*reinterpret_cast<__half2*>(&u));
}
__device__ __forceinline__ float h2lo(unsigned int u) {
    return __low2float(*reinterpret_cast<__half2*>(&u));
}

__global__ void __launch_bounds__(256) render_kernel(
    const float* __restrict__ depth,
    const float* __restrict__ background,
    float* __restrict__ out)
{
    int idx = blockIdx.x * blockDim.x + threadIdx.x;
    if (idx >= NPIX) return;

    int pix = idx % HW;
    int cam = idx / HW;       // = b*NR + n
    int b   = cam / NR;
    int obase = cam*3*HW + pix;

    float d = depth[idx];
    if (!(d > 0.0f)) {
        out[obase]        = background[obase];
        out[obase + HW]   = background[obase + HW];
        out[obase + 2*HW] = background[obase + 2*HW];
        return;
    }

    float fx = (float)(pix % IW);
    float fy = (float)(pix / IW);
    const float* M = g_renderM[cam];
    float nd = -d;
    float px = nd*(M[0]*fx + M[1]*fy + M[2]) - M[9];
    float py = nd*(M[3]*fx + M[4]*fy + M[5]) - M[10];
    float pz = nd*(M[6]*fx + M[7]*fy + M[8]) - M[11];

    float r0 = 0.0f, r1 = 0.0f, r2 = 0.0f;

    #pragma unroll
    for (int r = 0; r < NREF; r++) {
        const float* P = g_refP[b*NREF + r];
        float qx = P[0]*px + P[1]*py + P[2]*pz + P[9];
        float qy = P[3]*px + P[4]*py + P[5]*pz + P[10];
        float qz = P[6]*px + P[7]*py + P[8]*pz + P[11];
        float iz = __frcp_rn(qz);
        // Clamp into the padded domain. Out-of-range (or NaN) coords land on
        // the zero border with zero bilinear weight, reproducing the
        // reference's validity-mask semantics exactly.
        float u = fminf(fmaxf(qx*iz, -1.0f), 320.0f);
        float v = fminf(fmaxf(qy*iz, -1.0f), 320.0f);

        float x0 = floorf(u);
        float y0 = floorf(v);
        float wx = u - x0;
        float wy = v - y0;

        float w00 = (1.0f-wx)*(1.0f-wy);
        float w01 = wx*(1.0f-wy);
        float w10 = (1.0f-wx)*wy;
        float w11 = wx*wy;

        int base = ((int)y0 + 1)*PW + ((int)x0 + 1);

        const uint4* fm = g_imgp + (size_t)(b*NREF + r)*PHW;
        // One 16B load per bilinear row: lo half = texel x0, hi half = texel
        // x0+1 (always present in the padded layout).
        uint4 cA = __ldg(fm + base);        // row y0
        uint4 cB = __ldg(fm + base + PW);   // row y0+1

        float2 rg00 = h2f2(cA.x);
        float2 rg01 = h2f2(cA.z);
        float2 rg10 = h2f2(cB.x);
        float2 rg11 = h2f2(cB.z);

        r0 += w00*rg00.x + w01*rg01.x + w10*rg10.x + w11*rg11.x;
        r1 += w00*rg00.y + w01*rg01.y + w10*rg10.y + w11*rg11.y;
        r2 += w00*h2lo(cA.y) + w01*h2lo(cA.w) + w10*h2lo(cB.y) + w11*h2lo(cB.w);
    }

    const float sc = 1.0f / (float)NREF;
    out[obase]        = r0*sc;
    out[obase + HW]   = r1*sc;
    out[obase + 2*HW] = r2*sc;
}

extern "C" void kernel_launch(void* const* d_in, const int* in_sizes, int n_in,
                              void* d_out, int out_size) {
    const float* depth      = (const float*)d_in[0];
    const float* cam_K      = (const float*)d_in[1];
    const float* cam_W      = (const float*)d_in[2];
    const float* image_ref  = (const float*)d_in[3];
    const float* background = (const float*)d_in[4];
    // d_in[5] = cube_diagonal : divide/multiply cancels, unused
    const float* cam_K_ref  = (const float*)d_in[6];
    const float* cam_W_ref  = (const float*)d_in[7];

    interleave_kernel<<<(NIMG*PHW + 255) / 256, 256>>>(image_ref, cam_K, cam_W,
                                                       cam_K_ref, cam_W_ref);
    render_kernel<<<(NPIX + 255) / 256, 256>>>(depth, background, (float*)d_out);
}